// round 15
// baseline (speedup 1.0000x reference)
#include <cuda_runtime.h>
#include <cuda_bf16.h>
#include <cstdint>

#define N_ATOMS 50000
#define M_NBR   32
#define NE      (N_ATOMS * M_NBR)   // 1,600,000 edges
#define NBR_F   64
#define ATOM_F  128
#define SH_DIM  9
#define INV_SQRT_F 0.08838834764831845f

#define TILE_E        128            // edges per tile (8 warps x 16 edges)
#define TILES_PER_CTA 8
#define N_TILES_TOTAL (NE / TILE_E)              // 12500
#define N_EDGE_CTAS   ((N_TILES_TOTAL + TILES_PER_CTA - 1) / TILES_PER_CTA)  // 1563

// ---- edge-kernel smem layout (byte offsets from 1024-aligned base) ----
#define OFF_A_HI   0                 // 128 x 64 bf16, swizzled 128B rows (16384)
#define OFF_A_LO   16384             // 16384
#define OFF_B_HI   32768             // 64 x 64 bf16 row-major [k][j], swz (8192)
#define OFF_B_LO   40960             // 8192
#define OFF_BW     49152             // 32 x float4 {b1[2j],b1[2j+1],w2[2j],w2[2j+1]}
#define OFF_RAW    49664             // 128 x 64 f32 raw tile (32768)
#define EDGE_SMEM_USED 82432
#define EDGE_SMEM_BYTES (EDGE_SMEM_USED + 1024)

__device__ float g_S[N_ATOMS];
__device__ float g_C[N_ATOMS];

__global__ void zero_kernel() {
    int i = blockIdx.x * blockDim.x + threadIdx.x;
    if (i < N_ATOMS) { g_S[i] = 0.0f; g_C[i] = 0.0f; }
}

// ======================= helpers =======================
__device__ __forceinline__ uint32_t smem_u32(const void* p) {
    uint32_t a;
    asm("{ .reg .u64 t; cvta.to.shared.u64 t, %1; cvt.u32.u64 %0, t; }"
        : "=r"(a) : "l"(p));
    return a;
}
__device__ __forceinline__ void sts64(uint32_t addr, unsigned long long v) {
    asm volatile("st.shared.b64 [%0], %1;" :: "r"(addr), "l"(v) : "memory");
}
__device__ __forceinline__ void sts32(uint32_t addr, uint32_t v) {
    asm volatile("st.shared.b32 [%0], %1;" :: "r"(addr), "r"(v) : "memory");
}
__device__ __forceinline__ void sts16(uint32_t addr, unsigned short v) {
    asm volatile("st.shared.b16 [%0], %1;" :: "r"(addr), "h"(v) : "memory");
}
#define SMEM_SWZ(off) ((off) ^ (((off) >> 3) & 0x70))

__device__ __forceinline__ void ldsm_x4(uint32_t addr, uint32_t* r) {
    asm volatile("ldmatrix.sync.aligned.m8n8.x4.shared.b16 {%0,%1,%2,%3}, [%4];"
        : "=r"(r[0]), "=r"(r[1]), "=r"(r[2]), "=r"(r[3]) : "r"(addr));
}
__device__ __forceinline__ void ldsm_x2t(uint32_t addr, uint32_t& a, uint32_t& b) {
    asm volatile("ldmatrix.sync.aligned.m8n8.x2.trans.shared.b16 {%0,%1}, [%2];"
        : "=r"(a), "=r"(b) : "r"(addr));
}
// x4 trans: loads TWO n-tiles' B fragments (lanes 0-15 -> nt, 16-31 -> nt+1)
__device__ __forceinline__ void ldsm_x4t(uint32_t addr, uint32_t* r) {
    asm volatile("ldmatrix.sync.aligned.m8n8.x4.trans.shared.b16 {%0,%1,%2,%3}, [%4];"
        : "=r"(r[0]), "=r"(r[1]), "=r"(r[2]), "=r"(r[3]) : "r"(addr));
}
__device__ __forceinline__ void mma_bf16(float* d, const uint32_t* a,
                                         uint32_t b0, uint32_t b1) {
    asm volatile("mma.sync.aligned.m16n8k16.row.col.f32.bf16.bf16.f32 "
        "{%0,%1,%2,%3}, {%4,%5,%6,%7}, {%8,%9}, {%0,%1,%2,%3};"
        : "+f"(d[0]), "+f"(d[1]), "+f"(d[2]), "+f"(d[3])
        : "r"(a[0]), "r"(a[1]), "r"(a[2]), "r"(a[3]), "r"(b0), "r"(b1));
}
__device__ __forceinline__ unsigned short bf_bits(__nv_bfloat16 b) {
    return *reinterpret_cast<unsigned short*>(&b);
}
__device__ __forceinline__ uint32_t cvt_bf2(float hi, float lo) {
    uint32_t r;
    asm("cvt.rn.bf16x2.f32 %0, %1, %2;" : "=r"(r) : "f"(hi), "f"(lo));
    return r;
}
__device__ __forceinline__ unsigned long long pack64(uint32_t lo, uint32_t hi) {
    unsigned long long v;
    asm("mov.b64 %0, {%1, %2};" : "=l"(v) : "r"(lo), "r"(hi));
    return v;
}
__device__ __forceinline__ void cpasync16(uint32_t dst, const void* src) {
    asm volatile("cp.async.ca.shared.global [%0], [%1], 16;"
        :: "r"(dst), "l"(src) : "memory");
}
__device__ __forceinline__ void cpasync_commit() {
    asm volatile("cp.async.commit_group;" ::: "memory");
}
__device__ __forceinline__ void cpasync_wait0() {
    asm volatile("cp.async.wait_group 0;" ::: "memory");
}

// softplus(x) = max(x,0) + log1p(exp(-|x|)) with log1p replaced by the
// A&S 4.1.43 degree-5 minimax on u in [0,1]  (|err| <= 1e-5 abs).
// 1 MUFU (exp) instead of 2 (exp + log).
__device__ __forceinline__ float softplus_fast(float x) {
    float u = __expf(-fabsf(x));
    float p = fmaf(u, 0.03215845f, -0.13606275f);
    p = fmaf(u, p, 0.28947478f);
    p = fmaf(u, p, -0.49190896f);
    p = fmaf(u, p, 0.99949556f);
    return fmaxf(x, 0.0f) + u * p;
}

// ---------------------------------------------------------------------------
// Edge kernel — R10 structure (189 us) with poly-softplus epilogue.
// h = radial @ w1 on HMMA, 3-term bf16 hi/lo split, fp32 acc; cp.async
// double-buffered raw tiles; softplus . w2 epilogue + atomics.
// ---------------------------------------------------------------------------
__global__ __launch_bounds__(256, 2) void edge_kernel(
    const float* __restrict__ nbr_fea,
    const int*   __restrict__ nbr_idx,
    const float* __restrict__ w1,
    const float* __restrict__ b1,
    const float* __restrict__ w2,
    const float* __restrict__ b2)
{
    extern __shared__ char dyn[];
    const uint32_t raw_a = smem_u32(dyn);
    const uint32_t base  = (raw_a + 1023u) & ~1023u;
    char* bp = dyn + (base - raw_a);

    const int tid  = threadIdx.x;
    const int wid  = tid >> 5;
    const int lane = tid & 31;
    const int gid  = lane >> 2;     // row group 0-7
    const int tid4 = lane & 3;      // col group 0-3

    const int tile0   = blockIdx.x * TILES_PER_CTA;
    const int n_tiles = (tile0 + TILES_PER_CTA <= N_TILES_TOTAL)
                        ? TILES_PER_CTA : (N_TILES_TOTAL - tile0);
    if (n_tiles <= 0) return;

    // ---- stage B = w1 row-major [k][j], bf16 hi/lo, swizzled (once/CTA) ----
    #pragma unroll
    for (int it = 0; it < 16; it++) {
        int idx = it * 256 + tid;          // [0, 4096)
        int k = idx >> 6, j = idx & 63;
        float v = w1[idx];
        __nv_bfloat16 bh = __float2bfloat16(v);
        __nv_bfloat16 bl = __float2bfloat16(v - __bfloat162float(bh));
        uint32_t off = SMEM_SWZ((uint32_t)(k * 128 + j * 2));
        sts16(base + OFF_B_HI + off, bf_bits(bh));
        sts16(base + OFF_B_LO + off, bf_bits(bl));
    }
    if (tid < 32) {   // interleaved {b1[2t],b1[2t+1],w2[2t],w2[2t+1]}
        float4 bw;
        bw.x = b1[2 * tid];
        bw.y = b1[2 * tid + 1];
        bw.z = w2[(2 * tid) * SH_DIM];
        bw.w = w2[(2 * tid + 1) * SH_DIM];
        *(float4*)(bp + OFF_BW + tid * 16) = bw;
    }
    const float b2v = b2[0];

    // ---- async-prefetch tile 0 raw fp32 ----
    {
        const float* src = nbr_fea + (size_t)tile0 * TILE_E * NBR_F;
        #pragma unroll
        for (int it = 0; it < 8; it++) {
            int idx = it * 256 + tid;
            cpasync16(base + OFF_RAW + idx * 16, src + idx * 4);
        }
        cpasync_commit();
    }

    for (int t = 0; t < n_tiles; t++) {
        const int tb = (tile0 + t) * TILE_E;

        // hoist idx loads for this tile (consumed at epilogue end)
        int ia0 = 0, ia1 = 0;
        if (tid4 == 0) {
            int r0 = wid * 16 + gid;
            ia0 = nbr_idx[tb + r0];
            ia1 = nbr_idx[tb + r0 + 8];
        }

        cpasync_wait0();
        __syncthreads();   // raw tile ready; prev tile's ldsm reads done

        // ---- convert raw (smem) -> A bf16 hi/lo planes ----
        #pragma unroll
        for (int it = 0; it < 8; it++) {
            int idx = it * 256 + tid;      // [0, 2048) float4 quads
            int row = idx >> 4, q = idx & 15;
            float4 v = *(const float4*)(bp + OFF_RAW + idx * 16);
            uint32_t h01 = cvt_bf2(v.y, v.x);
            uint32_t h23 = cvt_bf2(v.w, v.z);
            float f0 = __uint_as_float(h01 << 16);
            float f1 = __uint_as_float(h01 & 0xffff0000u);
            float f2 = __uint_as_float(h23 << 16);
            float f3 = __uint_as_float(h23 & 0xffff0000u);
            uint32_t l01 = cvt_bf2(v.y - f1, v.x - f0);
            uint32_t l23 = cvt_bf2(v.w - f3, v.z - f2);
            uint32_t off = SMEM_SWZ((uint32_t)(row * 128 + q * 8));
            sts64(base + OFF_A_HI + off, pack64(h01, h23));
            sts64(base + OFF_A_LO + off, pack64(l01, l23));
        }
        __syncthreads();   // A ready; raw buffer free for refill

        // ---- kick off next tile's raw prefetch (overlaps mainloop) ----
        if (t + 1 < n_tiles) {
            const float* src = nbr_fea + (size_t)(tb + TILE_E) * NBR_F;
            #pragma unroll
            for (int it = 0; it < 8; it++) {
                int idx = it * 256 + tid;
                cpasync16(base + OFF_RAW + idx * 16, src + idx * 4);
            }
            cpasync_commit();
        }

        // ---- mainloop ----
        float acc[8][4];
        #pragma unroll
        for (int nt = 0; nt < 8; nt++)
            #pragma unroll
            for (int c = 0; c < 4; c++) acc[nt][c] = 0.0f;

        // Pass 1: (A_hi + A_lo) . B_hi — B fragment loaded once, used twice
        #pragma unroll
        for (int ks = 0; ks < 4; ks++) {
            uint32_t ah[4], al[4];
            uint32_t aoff = (uint32_t)((wid * 16 + (lane & 15)) * 128
                                       + ks * 32 + (lane >> 4) * 16);
            ldsm_x4(base + OFF_A_HI + SMEM_SWZ(aoff), ah);
            ldsm_x4(base + OFF_A_LO + SMEM_SWZ(aoff), al);
            #pragma unroll
            for (int nt = 0; nt < 8; nt++) {
                uint32_t boff = (uint32_t)((ks * 16 + (lane & 15)) * 128 + nt * 16);
                uint32_t b0, b1r;
                ldsm_x2t(base + OFF_B_HI + SMEM_SWZ(boff), b0, b1r);
                mma_bf16(acc[nt], ah, b0, b1r);
                mma_bf16(acc[nt], al, b0, b1r);
            }
        }
        // Pass 2: A_hi . B_lo
        #pragma unroll
        for (int ks = 0; ks < 4; ks++) {
            uint32_t ah[4];
            uint32_t aoff = (uint32_t)((wid * 16 + (lane & 15)) * 128
                                       + ks * 32 + (lane >> 4) * 16);
            ldsm_x4(base + OFF_A_HI + SMEM_SWZ(aoff), ah);
            #pragma unroll
            for (int nt = 0; nt < 8; nt++) {
                uint32_t boff = (uint32_t)((ks * 16 + (lane & 15)) * 128 + nt * 16);
                uint32_t b0, b1r;
                ldsm_x2t(base + OFF_B_LO + SMEM_SWZ(boff), b0, b1r);
                mma_bf16(acc[nt], ah, b0, b1r);
            }
        }

        // ---- epilogue: poly-softplus . w2, quad-reduce, atomics ----
        float s0 = 0.0f, s1 = 0.0f;
        #pragma unroll
        for (int nt = 0; nt < 8; nt++) {
            int colp = nt * 4 + tid4;     // float4 index = col/2
            float4 bw = *(const float4*)(bp + OFF_BW + colp * 16);
            float p0 = softplus_fast(acc[nt][0] + bw.x);   // row gid
            float p1 = softplus_fast(acc[nt][1] + bw.y);
            float p2 = softplus_fast(acc[nt][2] + bw.x);   // row gid+8
            float p3 = softplus_fast(acc[nt][3] + bw.y);
            s0 = fmaf(p0, bw.z, s0); s0 = fmaf(p1, bw.w, s0);
            s1 = fmaf(p2, bw.z, s1); s1 = fmaf(p3, bw.w, s1);
        }
        s0 += __shfl_xor_sync(0xffffffffu, s0, 1);
        s0 += __shfl_xor_sync(0xffffffffu, s0, 2);
        s1 += __shfl_xor_sync(0xffffffffu, s1, 1);
        s1 += __shfl_xor_sync(0xffffffffu, s1, 2);
        if (tid4 == 0) {
            int a0 = ia0;
            a0 = (a0 < 0) ? 0 : (a0 >= N_ATOMS ? N_ATOMS - 1 : a0);
            atomicAdd(&g_S[a0], s0 + b2v);
            atomicAdd(&g_C[a0], 1.0f);
            int a1 = ia1;
            a1 = (a1 < 0) ? 0 : (a1 >= N_ATOMS ? N_ATOMS - 1 : a1);
            atomicAdd(&g_S[a1], s1 + b2v);
            atomicAdd(&g_C[a1], 1.0f);
        }
    }
}

// ---------------------------------------------------------------------------
// Output GEMM on HMMA (R13 version, passing). 4 atom-tiles per CTA; tp_w
// staged once (float4 loads, bf16x2 pair stores); paired x4.trans B loads.
// ---------------------------------------------------------------------------
#define OT_M 64
#define OT_TILES 4
#define N_OUT_CTAS ((N_ATOMS + OT_M * OT_TILES - 1) / (OT_M * OT_TILES))   // 196

#define O_A_HI 0        // 2 kc-planes x 8192 (64 rows x 128B)
#define O_A_LO 16384
#define O_B_HI 32768    // 4 planes [kc][ch] x 8192
#define O_B_LO 65536
#define OUT_SMEM_USED 98304
#define OUT_SMEM_BYTES (OUT_SMEM_USED + 1024)

__global__ __launch_bounds__(256, 2) void out_kernel(
    const float* __restrict__ atom_fea,
    const float* __restrict__ tp_w,
    float* __restrict__ out)
{
    extern __shared__ char dyn[];
    const uint32_t raw_a = smem_u32(dyn);
    const uint32_t base  = (raw_a + 1023u) & ~1023u;

    const int tid  = threadIdx.x;
    const int wid  = tid >> 5;
    const int lane = tid & 31;
    const int gid  = lane >> 2;
    const int tid4 = lane & 3;
    const int mt   = wid & 3;       // m-tile (16 atoms)
    const int ch   = wid >> 2;      // col half (64 cols)

    // ---- stage B = tp_w [k][j] bf16 hi/lo into 4 planes [kc][jh] (once) ----
    {
        const float4* tw4 = (const float4*)tp_w;
        #pragma unroll
        for (int it = 0; it < 16; it++) {
            int fidx = it * 256 + tid;         // [0, 4096) float4s
            int k = fidx >> 5;                 // 32 float4 per 128-col row
            int jq = fidx & 31;
            int j = jq * 4;                    // j..j+3 same 64-col plane
            float4 v = tw4[fidx];
            uint32_t h01 = cvt_bf2(v.y, v.x);
            uint32_t h23 = cvt_bf2(v.w, v.z);
            float f0 = __uint_as_float(h01 << 16);
            float f1 = __uint_as_float(h01 & 0xffff0000u);
            float f2 = __uint_as_float(h23 << 16);
            float f3 = __uint_as_float(h23 & 0xffff0000u);
            uint32_t l01 = cvt_bf2(v.y - f1, v.x - f0);
            uint32_t l23 = cvt_bf2(v.w - f3, v.z - f2);
            uint32_t plane = (uint32_t)(((k >> 6) * 2 + (j >> 6)) * 8192);
            uint32_t o0 = plane + SMEM_SWZ((uint32_t)((k & 63) * 128 + (j & 63) * 2));
            uint32_t o1 = plane + SMEM_SWZ((uint32_t)((k & 63) * 128 + ((j + 2) & 63) * 2));
            sts32(base + O_B_HI + o0, h01);
            sts32(base + O_B_HI + o1, h23);
            sts32(base + O_B_LO + o0, l01);
            sts32(base + O_B_LO + o1, l23);
        }
    }

    for (int t = 0; t < OT_TILES; t++) {
        const int abase = (blockIdx.x * OT_TILES + t) * OT_M;
        if (abase >= N_ATOMS) break;

        __syncthreads();   // B ready (t==0) / prev tile's A reads done

        // ---- stage A tile (64 atoms x 128 k) bf16 hi/lo, 2 kc planes ----
        #pragma unroll
        for (int it = 0; it < 8; it++) {
            int idx = it * 256 + tid;          // [0, 2048) float4 quads
            int row = idx >> 5, q = idx & 31;
            int kc = q >> 4, qq = q & 15;
            int atom = abase + row;
            float4 v = make_float4(0.f, 0.f, 0.f, 0.f);
            if (atom < N_ATOMS)
                v = *(const float4*)(atom_fea + (size_t)atom * ATOM_F + q * 4);
            uint32_t h01 = cvt_bf2(v.y, v.x);
            uint32_t h23 = cvt_bf2(v.w, v.z);
            float f0 = __uint_as_float(h01 << 16);
            float f1 = __uint_as_float(h01 & 0xffff0000u);
            float f2 = __uint_as_float(h23 << 16);
            float f3 = __uint_as_float(h23 & 0xffff0000u);
            uint32_t l01 = cvt_bf2(v.y - f1, v.x - f0);
            uint32_t l23 = cvt_bf2(v.w - f3, v.z - f2);
            uint32_t off = (uint32_t)(kc * 8192)
                         + SMEM_SWZ((uint32_t)(row * 128 + qq * 8));
            sts64(base + O_A_HI + off, pack64(h01, h23));
            sts64(base + O_A_LO + off, pack64(l01, l23));
        }
        __syncthreads();

        // ---- mainloop: 2 k-chunks x 4 ks, paired-nt B loads ----
        float acc[8][4];
        #pragma unroll
        for (int nt = 0; nt < 8; nt++)
            #pragma unroll
            for (int c = 0; c < 4; c++) acc[nt][c] = 0.0f;

        #pragma unroll
        for (int kc = 0; kc < 2; kc++) {
            const uint32_t apl = (uint32_t)(kc * 8192);
            const uint32_t bpl = (uint32_t)((kc * 2 + ch) * 8192);
            #pragma unroll
            for (int ks = 0; ks < 4; ks++) {
                uint32_t ah[4], al[4];
                uint32_t aoff = apl + SMEM_SWZ((uint32_t)((mt * 16 + (lane & 15)) * 128
                                               + ks * 32 + (lane >> 4) * 16));
                ldsm_x4(base + O_A_HI + aoff, ah);
                ldsm_x4(base + O_A_LO + aoff, al);
                #pragma unroll
                for (int ntp = 0; ntp < 4; ntp++) {
                    uint32_t boff = bpl + SMEM_SWZ((uint32_t)((ks * 16 + (lane & 15)) * 128
                                                   + (ntp * 2 + (lane >> 4)) * 16));
                    uint32_t bh4[4], bl4[4];
                    ldsm_x4t(base + O_B_HI + boff, bh4);
                    ldsm_x4t(base + O_B_LO + boff, bl4);
                    mma_bf16(acc[2 * ntp],     ah, bh4[0], bh4[1]);
                    mma_bf16(acc[2 * ntp],     al, bh4[0], bh4[1]);
                    mma_bf16(acc[2 * ntp],     ah, bl4[0], bl4[1]);
                    mma_bf16(acc[2 * ntp + 1], ah, bh4[2], bh4[3]);
                    mma_bf16(acc[2 * ntp + 1], al, bh4[2], bh4[3]);
                    mma_bf16(acc[2 * ntp + 1], ah, bl4[2], bl4[3]);
                }
            }
        }

        // ---- epilogue: per-atom scale, write float2 pairs ----
        int atomA = abase + mt * 16 + gid;
        int atomB = atomA + 8;
        float scA = 0.0f, scB = 0.0f;
        if (atomA < N_ATOMS)
            scA = g_S[atomA] * INV_SQRT_F / fmaxf(g_C[atomA], 1.0f);
        if (atomB < N_ATOMS)
            scB = g_S[atomB] * INV_SQRT_F / fmaxf(g_C[atomB], 1.0f);

        #pragma unroll
        for (int nt = 0; nt < 8; nt++) {
            int col = ch * 64 + nt * 8 + tid4 * 2;
            if (atomA < N_ATOMS)
                *(float2*)(out + (size_t)atomA * ATOM_F + col) =
                    make_float2(acc[nt][0] * scA, acc[nt][1] * scA);
            if (atomB < N_ATOMS)
                *(float2*)(out + (size_t)atomB * ATOM_F + col) =
                    make_float2(acc[nt][2] * scB, acc[nt][3] * scB);
        }
    }
}

// ---------------------------------------------------------------------------
// Launch
// ---------------------------------------------------------------------------
extern "C" void kernel_launch(void* const* d_in, const int* in_sizes, int n_in,
                              void* d_out, int out_size)
{
    const float* atom_fea = (const float*)d_in[0];
    const float* nbr_fea  = (const float*)d_in[1];
    const int*   nbr_idx  = (const int*)d_in[2];
    const float* w1       = (const float*)d_in[3];
    const float* b1       = (const float*)d_in[4];
    const float* w2       = (const float*)d_in[5];
    const float* b2       = (const float*)d_in[6];
    const float* tp_w     = (const float*)d_in[7];
    float*       out      = (float*)d_out;

    cudaFuncSetAttribute(edge_kernel,
                         cudaFuncAttributeMaxDynamicSharedMemorySize,
                         EDGE_SMEM_BYTES);
    cudaFuncSetAttribute(out_kernel,
                         cudaFuncAttributeMaxDynamicSharedMemorySize,
                         OUT_SMEM_BYTES);

    zero_kernel<<<(N_ATOMS + 255) / 256, 256>>>();
    edge_kernel<<<N_EDGE_CTAS, 256, EDGE_SMEM_BYTES>>>(nbr_fea, nbr_idx,
                                                       w1, b1, w2, b2);
    out_kernel<<<N_OUT_CTAS, 256, OUT_SMEM_BYTES>>>(atom_fea, tp_w, out);
}

// round 16
// speedup vs baseline: 1.1117x; 1.1117x over previous
#include <cuda_runtime.h>
#include <cuda_bf16.h>
#include <cstdint>

#define N_ATOMS 50000
#define M_NBR   32
#define NE      (N_ATOMS * M_NBR)   // 1,600,000 edges
#define NBR_F   64
#define ATOM_F  128
#define SH_DIM  9
#define INV_SQRT_F 0.08838834764831845f

#define TILE_E        128            // edges per tile (8 warps x 16 edges)
#define TILES_PER_CTA 8
#define N_TILES_TOTAL (NE / TILE_E)              // 12500
#define N_EDGE_CTAS   ((N_TILES_TOTAL + TILES_PER_CTA - 1) / TILES_PER_CTA)  // 1563

// ---- edge-kernel smem layout (byte offsets from 1024-aligned base) ----
#define OFF_B_HI   0                 // 64 x 64 bf16 [k][j], swz 128B rows (8192)
#define OFF_B_LO   8192              // 8192
#define OFF_BW     16384             // 32 x float4 {b1,b1,w2,w2}
#define OFF_RAW0   17408             // 128 x 64 f32 raw tile, XOR-swz 16B (32768)
#define OFF_RAW1   50176             // second raw buffer (32768)
#define EDGE_SMEM_USED 82944
#define EDGE_SMEM_BYTES (EDGE_SMEM_USED + 1024)

__device__ float g_S[N_ATOMS];
__device__ float g_C[N_ATOMS];

__global__ void zero_kernel() {
    int i = blockIdx.x * blockDim.x + threadIdx.x;
    if (i < N_ATOMS) { g_S[i] = 0.0f; g_C[i] = 0.0f; }
}

// ======================= helpers =======================
__device__ __forceinline__ uint32_t smem_u32(const void* p) {
    uint32_t a;
    asm("{ .reg .u64 t; cvta.to.shared.u64 t, %1; cvt.u32.u64 %0, t; }"
        : "=r"(a) : "l"(p));
    return a;
}
__device__ __forceinline__ void sts64(uint32_t addr, unsigned long long v) {
    asm volatile("st.shared.b64 [%0], %1;" :: "r"(addr), "l"(v) : "memory");
}
__device__ __forceinline__ void sts32(uint32_t addr, uint32_t v) {
    asm volatile("st.shared.b32 [%0], %1;" :: "r"(addr), "r"(v) : "memory");
}
__device__ __forceinline__ void sts16(uint32_t addr, unsigned short v) {
    asm volatile("st.shared.b16 [%0], %1;" :: "r"(addr), "h"(v) : "memory");
}
__device__ __forceinline__ float2 lds_f2(uint32_t addr) {
    float2 v;
    asm volatile("ld.shared.v2.f32 {%0,%1}, [%2];" : "=f"(v.x), "=f"(v.y) : "r"(addr));
    return v;
}
#define SMEM_SWZ(off) ((off) ^ (((off) >> 3) & 0x70))

__device__ __forceinline__ void ldsm_x4(uint32_t addr, uint32_t* r) {
    asm volatile("ldmatrix.sync.aligned.m8n8.x4.shared.b16 {%0,%1,%2,%3}, [%4];"
        : "=r"(r[0]), "=r"(r[1]), "=r"(r[2]), "=r"(r[3]) : "r"(addr));
}
__device__ __forceinline__ void ldsm_x2t(uint32_t addr, uint32_t& a, uint32_t& b) {
    asm volatile("ldmatrix.sync.aligned.m8n8.x2.trans.shared.b16 {%0,%1}, [%2];"
        : "=r"(a), "=r"(b) : "r"(addr));
}
__device__ __forceinline__ void ldsm_x4t(uint32_t addr, uint32_t* r) {
    asm volatile("ldmatrix.sync.aligned.m8n8.x4.trans.shared.b16 {%0,%1,%2,%3}, [%4];"
        : "=r"(r[0]), "=r"(r[1]), "=r"(r[2]), "=r"(r[3]) : "r"(addr));
}
__device__ __forceinline__ void mma_bf16(float* d, const uint32_t* a,
                                         uint32_t b0, uint32_t b1) {
    asm volatile("mma.sync.aligned.m16n8k16.row.col.f32.bf16.bf16.f32 "
        "{%0,%1,%2,%3}, {%4,%5,%6,%7}, {%8,%9}, {%0,%1,%2,%3};"
        : "+f"(d[0]), "+f"(d[1]), "+f"(d[2]), "+f"(d[3])
        : "r"(a[0]), "r"(a[1]), "r"(a[2]), "r"(a[3]), "r"(b0), "r"(b1));
}
__device__ __forceinline__ unsigned short bf_bits(__nv_bfloat16 b) {
    return *reinterpret_cast<unsigned short*>(&b);
}
__device__ __forceinline__ uint32_t cvt_bf2(float hi, float lo) {
    uint32_t r;
    asm("cvt.rn.bf16x2.f32 %0, %1, %2;" : "=r"(r) : "f"(hi), "f"(lo));
    return r;
}
__device__ __forceinline__ unsigned long long pack64(uint32_t lo, uint32_t hi) {
    unsigned long long v;
    asm("mov.b64 %0, {%1, %2};" : "=l"(v) : "r"(lo), "r"(hi));
    return v;
}
__device__ __forceinline__ void cpasync16(uint32_t dst, const void* src) {
    asm volatile("cp.async.ca.shared.global [%0], [%1], 16;"
        :: "r"(dst), "l"(src) : "memory");
}
__device__ __forceinline__ void cpasync_commit() {
    asm volatile("cp.async.commit_group;" ::: "memory");
}
__device__ __forceinline__ void cpasync_wait(int n) {
    if (n == 0) asm volatile("cp.async.wait_group 0;" ::: "memory");
    else        asm volatile("cp.async.wait_group 1;" ::: "memory");
}

// Convert a float2 (cols c, c+1) into a bf16x2 hi fragment + lo residual.
__device__ __forceinline__ void cvt_hilo(float2 v, uint32_t& hi, uint32_t& lo) {
    hi = cvt_bf2(v.y, v.x);
    float r0 = __uint_as_float(hi << 16);
    float r1 = __uint_as_float(hi & 0xffff0000u);
    lo = cvt_bf2(v.y - r1, v.x - r0);
}

// ---------------------------------------------------------------------------
// Edge kernel: h = radial @ w1 on HMMA, 3-term bf16 hi/lo split, fp32 acc.
// A fragments built DIRECTLY from the raw fp32 tile in smem (no A planes,
// no A-ldmatrix, one fewer barrier per tile). Raw tiles double-buffered via
// cp.async with 16B XOR swizzle for conflict-free fragment reads.
// ---------------------------------------------------------------------------
__global__ __launch_bounds__(256, 2) void edge_kernel(
    const float* __restrict__ nbr_fea,
    const int*   __restrict__ nbr_idx,
    const float* __restrict__ w1,
    const float* __restrict__ b1,
    const float* __restrict__ w2,
    const float* __restrict__ b2)
{
    extern __shared__ char dyn[];
    const uint32_t raw_a = smem_u32(dyn);
    const uint32_t base  = (raw_a + 1023u) & ~1023u;
    char* bp = dyn + (base - raw_a);

    const int tid  = threadIdx.x;
    const int wid  = tid >> 5;
    const int lane = tid & 31;
    const int gid  = lane >> 2;     // row group 0-7
    const int tid4 = lane & 3;      // col group 0-3

    const int tile0   = blockIdx.x * TILES_PER_CTA;
    const int n_tiles = (tile0 + TILES_PER_CTA <= N_TILES_TOTAL)
                        ? TILES_PER_CTA : (N_TILES_TOTAL - tile0);
    if (n_tiles <= 0) return;

    // ---- stage B = w1 row-major [k][j], bf16 hi/lo, swizzled (once/CTA) ----
    #pragma unroll
    for (int it = 0; it < 16; it++) {
        int idx = it * 256 + tid;          // [0, 4096)
        int k = idx >> 6, j = idx & 63;
        float v = w1[idx];
        __nv_bfloat16 bh = __float2bfloat16(v);
        __nv_bfloat16 bl = __float2bfloat16(v - __bfloat162float(bh));
        uint32_t off = SMEM_SWZ((uint32_t)(k * 128 + j * 2));
        sts16(base + OFF_B_HI + off, bf_bits(bh));
        sts16(base + OFF_B_LO + off, bf_bits(bl));
    }
    if (tid < 32) {   // interleaved {b1[2t],b1[2t+1],w2[2t],w2[2t+1]}
        float4 bw;
        bw.x = b1[2 * tid];
        bw.y = b1[2 * tid + 1];
        bw.z = w2[(2 * tid) * SH_DIM];
        bw.w = w2[(2 * tid + 1) * SH_DIM];
        *(float4*)(bp + OFF_BW + tid * 16) = bw;
    }
    const float b2v = b2[0];

    // ---- async-prefetch tile 0 raw fp32 into RAW0 (XOR-swizzled 16B) ----
    {
        const float* src = nbr_fea + (size_t)tile0 * TILE_E * NBR_F;
        #pragma unroll
        for (int it = 0; it < 8; it++) {
            int idx = it * 256 + tid;
            int row = idx >> 4, q = idx & 15;
            uint32_t dst = base + OFF_RAW0 + row * 256
                         + (((uint32_t)(q * 16)) ^ ((uint32_t)(row & 7) << 4));
            cpasync16(dst, src + idx * 4);
        }
        cpasync_commit();
    }

    for (int t = 0; t < n_tiles; t++) {
        const int tb = (tile0 + t) * TILE_E;
        const uint32_t rb = base + ((t & 1) ? OFF_RAW1 : OFF_RAW0);

        // hoist idx loads for this tile (consumed at epilogue end)
        int ia0 = 0, ia1 = 0;
        if (tid4 == 0) {
            int r0 = wid * 16 + gid;
            ia0 = nbr_idx[tb + r0];
            ia1 = nbr_idx[tb + r0 + 8];
        }

        __syncthreads();   // prev tile's raw reads done -> other buffer free

        // ---- prefetch next tile into the other buffer ----
        if (t + 1 < n_tiles) {
            const float* src = nbr_fea + (size_t)(tb + TILE_E) * NBR_F;
            const uint32_t nb = base + (((t + 1) & 1) ? OFF_RAW1 : OFF_RAW0);
            #pragma unroll
            for (int it = 0; it < 8; it++) {
                int idx = it * 256 + tid;
                int row = idx >> 4, q = idx & 15;
                uint32_t dst = nb + row * 256
                             + (((uint32_t)(q * 16)) ^ ((uint32_t)(row & 7) << 4));
                cpasync16(dst, src + idx * 4);
            }
            cpasync_commit();
            cpasync_wait(1);   // tile t's group complete (next still in flight)
        } else {
            cpasync_wait(0);
        }
        __syncthreads();   // tile t's raw visible to all threads

        // ---- mainloop: fragments converted in registers, 3 bf16 terms ----
        float acc[8][4];
        #pragma unroll
        for (int nt = 0; nt < 8; nt++)
            #pragma unroll
            for (int c = 0; c < 4; c++) acc[nt][c] = 0.0f;

        const uint32_t a_r0 = rb + (uint32_t)(wid * 16 + gid) * 256;
        const uint32_t a_r1 = a_r0 + 8 * 256;
        const uint32_t sx   = (uint32_t)gid << 4;

        #pragma unroll
        for (int ks = 0; ks < 4; ks++) {
            uint32_t o0 = ((uint32_t)(ks * 64 + tid4 * 8)) ^ sx;
            uint32_t o1 = o0 ^ 32u;
            float2 v00 = lds_f2(a_r0 + o0);   // row gid,   cols c0,c0+1
            float2 v10 = lds_f2(a_r1 + o0);   // row gid+8, cols c0,c0+1
            float2 v01 = lds_f2(a_r0 + o1);   // row gid,   cols c0+8,+9
            float2 v11 = lds_f2(a_r1 + o1);   // row gid+8, cols c0+8,+9
            uint32_t ah[4], al[4];
            cvt_hilo(v00, ah[0], al[0]);
            cvt_hilo(v10, ah[1], al[1]);
            cvt_hilo(v01, ah[2], al[2]);
            cvt_hilo(v11, ah[3], al[3]);

            #pragma unroll
            for (int nt = 0; nt < 8; nt++) {
                uint32_t boff = (uint32_t)((ks * 16 + (lane & 15)) * 128 + nt * 16);
                uint32_t b0, b1r;
                ldsm_x2t(base + OFF_B_HI + SMEM_SWZ(boff), b0, b1r);
                mma_bf16(acc[nt], ah, b0, b1r);
                mma_bf16(acc[nt], al, b0, b1r);
                ldsm_x2t(base + OFF_B_LO + SMEM_SWZ(boff), b0, b1r);
                mma_bf16(acc[nt], ah, b0, b1r);
            }
        }

        // ---- epilogue: softplus . w2, quad-reduce, atomics ----
        float s0 = 0.0f, s1 = 0.0f;
        #pragma unroll
        for (int nt = 0; nt < 8; nt++) {
            int colp = nt * 4 + tid4;     // float4 index = col/2
            float4 bw = *(const float4*)(bp + OFF_BW + colp * 16);
            float h0 = acc[nt][0] + bw.x;   // row gid
            float h1 = acc[nt][1] + bw.y;
            float h2 = acc[nt][2] + bw.x;   // row gid+8
            float h3 = acc[nt][3] + bw.y;
            float p0 = fmaxf(h0, 0.0f) + __logf(1.0f + __expf(-fabsf(h0)));
            float p1 = fmaxf(h1, 0.0f) + __logf(1.0f + __expf(-fabsf(h1)));
            float p2 = fmaxf(h2, 0.0f) + __logf(1.0f + __expf(-fabsf(h2)));
            float p3 = fmaxf(h3, 0.0f) + __logf(1.0f + __expf(-fabsf(h3)));
            s0 = fmaf(p0, bw.z, s0); s0 = fmaf(p1, bw.w, s0);
            s1 = fmaf(p2, bw.z, s1); s1 = fmaf(p3, bw.w, s1);
        }
        s0 += __shfl_xor_sync(0xffffffffu, s0, 1);
        s0 += __shfl_xor_sync(0xffffffffu, s0, 2);
        s1 += __shfl_xor_sync(0xffffffffu, s1, 1);
        s1 += __shfl_xor_sync(0xffffffffu, s1, 2);
        if (tid4 == 0) {
            int a0 = ia0;
            a0 = (a0 < 0) ? 0 : (a0 >= N_ATOMS ? N_ATOMS - 1 : a0);
            atomicAdd(&g_S[a0], s0 + b2v);
            atomicAdd(&g_C[a0], 1.0f);
            int a1 = ia1;
            a1 = (a1 < 0) ? 0 : (a1 >= N_ATOMS ? N_ATOMS - 1 : a1);
            atomicAdd(&g_S[a1], s1 + b2v);
            atomicAdd(&g_C[a1], 1.0f);
        }
    }
}

// ---------------------------------------------------------------------------
// Output GEMM on HMMA (R13 version, passing). 4 atom-tiles per CTA; tp_w
// staged once (float4 loads, bf16x2 pair stores); paired x4.trans B loads.
// ---------------------------------------------------------------------------
#define OT_M 64
#define OT_TILES 4
#define N_OUT_CTAS ((N_ATOMS + OT_M * OT_TILES - 1) / (OT_M * OT_TILES))   // 196

#define O_A_HI 0        // 2 kc-planes x 8192 (64 rows x 128B)
#define O_A_LO 16384
#define O_B_HI 32768    // 4 planes [kc][ch] x 8192
#define O_B_LO 65536
#define OUT_SMEM_USED 98304
#define OUT_SMEM_BYTES (OUT_SMEM_USED + 1024)

__global__ __launch_bounds__(256, 2) void out_kernel(
    const float* __restrict__ atom_fea,
    const float* __restrict__ tp_w,
    float* __restrict__ out)
{
    extern __shared__ char dyn[];
    const uint32_t raw_a = smem_u32(dyn);
    const uint32_t base  = (raw_a + 1023u) & ~1023u;

    const int tid  = threadIdx.x;
    const int wid  = tid >> 5;
    const int lane = tid & 31;
    const int gid  = lane >> 2;
    const int tid4 = lane & 3;
    const int mt   = wid & 3;       // m-tile (16 atoms)
    const int ch   = wid >> 2;      // col half (64 cols)

    // ---- stage B = tp_w [k][j] bf16 hi/lo into 4 planes [kc][jh] (once) ----
    {
        const float4* tw4 = (const float4*)tp_w;
        #pragma unroll
        for (int it = 0; it < 16; it++) {
            int fidx = it * 256 + tid;         // [0, 4096) float4s
            int k = fidx >> 5;                 // 32 float4 per 128-col row
            int jq = fidx & 31;
            int j = jq * 4;                    // j..j+3 same 64-col plane
            float4 v = tw4[fidx];
            uint32_t h01 = cvt_bf2(v.y, v.x);
            uint32_t h23 = cvt_bf2(v.w, v.z);
            float f0 = __uint_as_float(h01 << 16);
            float f1 = __uint_as_float(h01 & 0xffff0000u);
            float f2 = __uint_as_float(h23 << 16);
            float f3 = __uint_as_float(h23 & 0xffff0000u);
            uint32_t l01 = cvt_bf2(v.y - f1, v.x - f0);
            uint32_t l23 = cvt_bf2(v.w - f3, v.z - f2);
            uint32_t plane = (uint32_t)(((k >> 6) * 2 + (j >> 6)) * 8192);
            uint32_t o0 = plane + SMEM_SWZ((uint32_t)((k & 63) * 128 + (j & 63) * 2));
            uint32_t o1 = plane + SMEM_SWZ((uint32_t)((k & 63) * 128 + ((j + 2) & 63) * 2));
            sts32(base + O_B_HI + o0, h01);
            sts32(base + O_B_HI + o1, h23);
            sts32(base + O_B_LO + o0, l01);
            sts32(base + O_B_LO + o1, l23);
        }
    }

    for (int t = 0; t < OT_TILES; t++) {
        const int abase = (blockIdx.x * OT_TILES + t) * OT_M;
        if (abase >= N_ATOMS) break;

        __syncthreads();   // B ready (t==0) / prev tile's A reads done

        // ---- stage A tile (64 atoms x 128 k) bf16 hi/lo, 2 kc planes ----
        #pragma unroll
        for (int it = 0; it < 8; it++) {
            int idx = it * 256 + tid;          // [0, 2048) float4 quads
            int row = idx >> 5, q = idx & 31;
            int kc = q >> 4, qq = q & 15;
            int atom = abase + row;
            float4 v = make_float4(0.f, 0.f, 0.f, 0.f);
            if (atom < N_ATOMS)
                v = *(const float4*)(atom_fea + (size_t)atom * ATOM_F + q * 4);
            uint32_t h01 = cvt_bf2(v.y, v.x);
            uint32_t h23 = cvt_bf2(v.w, v.z);
            float f0 = __uint_as_float(h01 << 16);
            float f1 = __uint_as_float(h01 & 0xffff0000u);
            float f2 = __uint_as_float(h23 << 16);
            float f3 = __uint_as_float(h23 & 0xffff0000u);
            uint32_t l01 = cvt_bf2(v.y - f1, v.x - f0);
            uint32_t l23 = cvt_bf2(v.w - f3, v.z - f2);
            uint32_t off = (uint32_t)(kc * 8192)
                         + SMEM_SWZ((uint32_t)(row * 128 + qq * 8));
            sts64(base + O_A_HI + off, pack64(h01, h23));
            sts64(base + O_A_LO + off, pack64(l01, l23));
        }
        __syncthreads();

        // ---- mainloop: 2 k-chunks x 4 ks, paired-nt B loads ----
        float acc[8][4];
        #pragma unroll
        for (int nt = 0; nt < 8; nt++)
            #pragma unroll
            for (int c = 0; c < 4; c++) acc[nt][c] = 0.0f;

        #pragma unroll
        for (int kc = 0; kc < 2; kc++) {
            const uint32_t apl = (uint32_t)(kc * 8192);
            const uint32_t bpl = (uint32_t)((kc * 2 + ch) * 8192);
            #pragma unroll
            for (int ks = 0; ks < 4; ks++) {
                uint32_t ah[4], al[4];
                uint32_t aoff = apl + SMEM_SWZ((uint32_t)((mt * 16 + (lane & 15)) * 128
                                               + ks * 32 + (lane >> 4) * 16));
                ldsm_x4(base + O_A_HI + aoff, ah);
                ldsm_x4(base + O_A_LO + aoff, al);
                #pragma unroll
                for (int ntp = 0; ntp < 4; ntp++) {
                    uint32_t boff = bpl + SMEM_SWZ((uint32_t)((ks * 16 + (lane & 15)) * 128
                                                   + (ntp * 2 + (lane >> 4)) * 16));
                    uint32_t bh4[4], bl4[4];
                    ldsm_x4t(base + O_B_HI + boff, bh4);
                    ldsm_x4t(base + O_B_LO + boff, bl4);
                    mma_bf16(acc[2 * ntp],     ah, bh4[0], bh4[1]);
                    mma_bf16(acc[2 * ntp],     al, bh4[0], bh4[1]);
                    mma_bf16(acc[2 * ntp],     ah, bl4[0], bl4[1]);
                    mma_bf16(acc[2 * ntp + 1], ah, bh4[2], bh4[3]);
                    mma_bf16(acc[2 * ntp + 1], al, bh4[2], bh4[3]);
                    mma_bf16(acc[2 * ntp + 1], ah, bl4[2], bl4[3]);
                }
            }
        }

        // ---- epilogue: per-atom scale, write float2 pairs ----
        int atomA = abase + mt * 16 + gid;
        int atomB = atomA + 8;
        float scA = 0.0f, scB = 0.0f;
        if (atomA < N_ATOMS)
            scA = g_S[atomA] * INV_SQRT_F / fmaxf(g_C[atomA], 1.0f);
        if (atomB < N_ATOMS)
            scB = g_S[atomB] * INV_SQRT_F / fmaxf(g_C[atomB], 1.0f);

        #pragma unroll
        for (int nt = 0; nt < 8; nt++) {
            int col = ch * 64 + nt * 8 + tid4 * 2;
            if (atomA < N_ATOMS)
                *(float2*)(out + (size_t)atomA * ATOM_F + col) =
                    make_float2(acc[nt][0] * scA, acc[nt][1] * scA);
            if (atomB < N_ATOMS)
                *(float2*)(out + (size_t)atomB * ATOM_F + col) =
                    make_float2(acc[nt][2] * scB, acc[nt][3] * scB);
        }
    }
}

// ---------------------------------------------------------------------------
// Launch
// ---------------------------------------------------------------------------
extern "C" void kernel_launch(void* const* d_in, const int* in_sizes, int n_in,
                              void* d_out, int out_size)
{
    const float* atom_fea = (const float*)d_in[0];
    const float* nbr_fea  = (const float*)d_in[1];
    const int*   nbr_idx  = (const int*)d_in[2];
    const float* w1       = (const float*)d_in[3];
    const float* b1       = (const float*)d_in[4];
    const float* w2       = (const float*)d_in[5];
    const float* b2       = (const float*)d_in[6];
    const float* tp_w     = (const float*)d_in[7];
    float*       out      = (float*)d_out;

    cudaFuncSetAttribute(edge_kernel,
                         cudaFuncAttributeMaxDynamicSharedMemorySize,
                         EDGE_SMEM_BYTES);
    cudaFuncSetAttribute(out_kernel,
                         cudaFuncAttributeMaxDynamicSharedMemorySize,
                         OUT_SMEM_BYTES);

    zero_kernel<<<(N_ATOMS + 255) / 256, 256>>>();
    edge_kernel<<<N_EDGE_CTAS, 256, EDGE_SMEM_BYTES>>>(nbr_fea, nbr_idx,
                                                       w1, b1, w2, b2);
    out_kernel<<<N_OUT_CTAS, 256, OUT_SMEM_BYTES>>>(atom_fea, tp_w, out);
}